// round 1
// baseline (speedup 1.0000x reference)
#include <cuda_runtime.h>
#include <cstring>

#define NLAYERS 200
#define KSIZE   7
#define L_IN    1388
#define FC_IN   188
#define FC_OUT  91
#define NT      128     // threads per block
#define CHUNK   11      // elements per thread (128*11 = 1408 >= 1388)
#define STAGE_N 1416    // 1408 + 8 pad so chunk+halo reads stay in bounds

// Packed dual-fp32 FMA (Blackwell f32x2). ptxas never emits this from C++;
// it doubles fp32 FMA throughput (rt_SMSP 1 instr / 2 FMAs vs 1/1).
static __device__ __forceinline__ float2 ffma2(float2 a, float2 b, float2 c) {
    unsigned long long ua, ub, uc, ud;
    memcpy(&ua, &a, 8); memcpy(&ub, &b, 8); memcpy(&uc, &c, 8);
    asm("fma.rn.f32x2 %0, %1, %2, %3;" : "=l"(ud) : "l"(ua), "l"(ub), "l"(uc));
    float2 d; memcpy(&d, &ud, 8);
    return d;
}

__global__ __launch_bounds__(NT, 4)
void conv200_kernel(const float* __restrict__ x,
                    const float* __restrict__ conv_w,
                    const float* __restrict__ conv_b,
                    const float* __restrict__ fc_w,
                    const float* __restrict__ fc_b,
                    float* __restrict__ out)
{
    __shared__ float2 stage[STAGE_N];          // input staging / final FC input
    __shared__ float2 halo[2][NT * 6];         // double-buffered halo exchange
    __shared__ float  ws[NLAYERS * KSIZE];
    __shared__ float  bs[NLAYERS];

    const int t   = threadIdx.x;
    const int blk = blockIdx.x;
    const int r0  = 2 * blk;

    const float* x0 = x + (size_t)r0 * L_IN;
    const float* x1 = x0 + L_IN;

    // Stage conv weights/biases into smem (broadcast reads in the layer loop).
    for (int j = t; j < NLAYERS * KSIZE; j += NT) ws[j] = conv_w[j];
    for (int j = t; j < NLAYERS;         j += NT) bs[j] = conv_b[j];

    // Coalesced load of the two rows, packed as float2 {row0, row1}; zero pad.
    for (int j = t; j < STAGE_N; j += NT) {
        float2 v;
        v.x = (j < L_IN) ? x0[j] : 0.0f;
        v.y = (j < L_IN) ? x1[j] : 0.0f;
        stage[j] = v;
    }
    __syncthreads();

    // Register-resident chunk: global indices [base, base+CHUNK)
    const int base = t * CHUNK;
    float2 a[CHUNK];
    #pragma unroll
    for (int c = 0; c < CHUNK; c++) a[c] = stage[base + c];

    // ---- 200 sequential conv layers ----
    // V = valid output length of layer i = 1382 - 6*i.
    int V = L_IN - (KSIZE - 1);   // 1382
    #pragma unroll 1
    for (int i = 0; i < NLAYERS; i++) {
        // Publish my first 6 elements (needed as left-halo by thread t-1)
        // whenever my data is still part of the valid input (length V+6).
        if (base < V + 6) {
            #pragma unroll
            for (int c = 0; c < 6; c++) halo[i & 1][t * 6 + c] = a[c];
        }
        __syncthreads();

        if (base < V) {
            float2 h[6];
            #pragma unroll
            for (int c = 0; c < 6; c++) h[c] = halo[i & 1][(t + 1) * 6 + c];

            float2 wp[KSIZE];
            #pragma unroll
            for (int k = 0; k < KSIZE; k++) {
                float w = ws[i * KSIZE + k];
                wp[k] = make_float2(w, w);
            }
            const float bias = bs[i];
            const bool  do_relu = (i < NLAYERS - 1);

            float2 na[CHUNK];
            #pragma unroll
            for (int c = 0; c < CHUNK; c++) {
                float2 acc = make_float2(bias, bias);
                #pragma unroll
                for (int k = 0; k < KSIZE; k++) {
                    float2 v = (c + k < CHUNK) ? a[c + k] : h[c + k - CHUNK];
                    acc = ffma2(wp[k], v, acc);
                }
                na[c] = acc;
            }
            if (do_relu) {
                #pragma unroll
                for (int c = 0; c < CHUNK; c++) {
                    na[c].x = fmaxf(na[c].x, 0.0f);   // FMNMX -> alu pipe, overlaps FFMA
                    na[c].y = fmaxf(na[c].y, 0.0f);
                }
            }
            #pragma unroll
            for (int c = 0; c < CHUNK; c++) a[c] = na[c];
        }
        V -= 6;
    }

    // ---- FC 188 -> 91 + sigmoid ----
    // Gather the final 188 valid elements into smem.
    if (base < FC_IN) {
        #pragma unroll
        for (int c = 0; c < CHUNK; c++)
            if (base + c < FC_IN) stage[base + c] = a[c];
    }
    __syncthreads();

    if (t < FC_OUT) {
        const float bb = __ldg(&fc_b[t]);
        float2 acc = make_float2(bb, bb);
        const float4* wrow = reinterpret_cast<const float4*>(fc_w + (size_t)t * FC_IN);
        #pragma unroll 4
        for (int j4 = 0; j4 < FC_IN / 4; j4++) {
            float4 w4 = __ldg(&wrow[j4]);
            int j = j4 * 4;
            acc = ffma2(make_float2(w4.x, w4.x), stage[j + 0], acc);
            acc = ffma2(make_float2(w4.y, w4.y), stage[j + 1], acc);
            acc = ffma2(make_float2(w4.z, w4.z), stage[j + 2], acc);
            acc = ffma2(make_float2(w4.w, w4.w), stage[j + 3], acc);
        }
        out[(size_t)r0       * FC_OUT + t] = 1.0f / (1.0f + __expf(-acc.x));
        out[(size_t)(r0 + 1) * FC_OUT + t] = 1.0f / (1.0f + __expf(-acc.y));
    }
}

extern "C" void kernel_launch(void* const* d_in, const int* in_sizes, int n_in,
                              void* d_out, int out_size)
{
    const float* x      = (const float*)d_in[0];   // [1024, 1388]
    const float* conv_w = (const float*)d_in[1];   // [200, 7]
    const float* conv_b = (const float*)d_in[2];   // [200]
    const float* fc_w   = (const float*)d_in[3];   // [91, 188]
    const float* fc_b   = (const float*)d_in[4];   // [91]
    float* out          = (float*)d_out;           // [1024, 91]

    const int B = in_sizes[0] / L_IN;              // 1024
    conv200_kernel<<<B / 2, NT>>>(x, conv_w, conv_b, fc_w, fc_b, out);
}